// round 5
// baseline (speedup 1.0000x reference)
#include <cuda_runtime.h>
#include <cuda_bf16.h>
#include <math.h>
#include <stdint.h>

#define K_DIM   2048
#define N_DIM   160
#define NC      10
#define DC      16
#define BM      64
#define BK      32
#define NCHUNK  (K_DIM / BK)          // 64
#define NTHREAD 256
#define HAT_STRIDE 165

// stage layout (bytes), rows padded to 80B for conflict-free ldmatrix
#define A_HI    0
#define A_LO    5120
#define B_HI    10240
#define B_LO    23040
#define STAGE_BYTES 35840
#define SMEM_TOTAL  (2 * STAGE_BYTES)   // 71680; hat tile 64*165*4=42240 fits

// Precomputed transposed split weights: Wt[n][k] = W[k][n]
__device__ __nv_bfloat16 g_Wt_hi[N_DIM * K_DIM];
__device__ __nv_bfloat16 g_Wt_lo[N_DIM * K_DIM];

// ---------------- helpers ----------------
__device__ __forceinline__ uint32_t smem_u32(const void* p) {
    uint32_t a;
    asm("{ .reg .u64 t; cvta.to.shared.u64 t, %1; cvt.u32.u64 %0, t; }" : "=r"(a) : "l"(p));
    return a;
}
__device__ __forceinline__ void ldsm4(uint32_t* d, uint32_t addr) {
    asm volatile("ldmatrix.sync.aligned.m8n8.x4.shared.b16 {%0,%1,%2,%3}, [%4];"
                 : "=r"(d[0]), "=r"(d[1]), "=r"(d[2]), "=r"(d[3]) : "r"(addr));
}
__device__ __forceinline__ void mma16816(float* c, const uint32_t* a,
                                         uint32_t b0, uint32_t b1) {
    asm volatile("mma.sync.aligned.m16n8k16.row.col.f32.bf16.bf16.f32 "
                 "{%0,%1,%2,%3}, {%4,%5,%6,%7}, {%8,%9}, {%0,%1,%2,%3};"
                 : "+f"(c[0]), "+f"(c[1]), "+f"(c[2]), "+f"(c[3])
                 : "r"(a[0]), "r"(a[1]), "r"(a[2]), "r"(a[3]), "r"(b0), "r"(b1));
}
__device__ __forceinline__ void cp_async16(uint32_t smem_dst, const void* gsrc) {
    asm volatile("cp.async.cg.shared.global [%0], [%1], 16;"
                 :: "r"(smem_dst), "l"(__cvta_generic_to_global(gsrc)) : "memory");
}
#define CP_COMMIT() asm volatile("cp.async.commit_group;" ::: "memory")
#define CP_WAIT0()  asm volatile("cp.async.wait_group 0;" ::: "memory")

__device__ __forceinline__ uint32_t pack_bf2(float x, float y) {
    __nv_bfloat162 t = __floats2bfloat162_rn(x, y);
    return *reinterpret_cast<uint32_t*>(&t);
}

// ---------------- pre-kernel: split + transpose W ----------------
__global__ void wt_split_kernel(const float* __restrict__ wk) {
    int idx = blockIdx.x * 256 + threadIdx.x;
    if (idx < N_DIM * K_DIM) {
        int n = idx / K_DIM;
        int k = idx % K_DIM;
        float v = wk[(size_t)k * N_DIM + n];
        __nv_bfloat16 hi = __float2bfloat16(v);
        g_Wt_hi[idx] = hi;
        g_Wt_lo[idx] = __float2bfloat16(v - __bfloat162float(hi));
    }
}

// term-major over a pair of B groups: same-acc RAW distance = 4
#define MMA_PAIR(AH, AL, BH0, BH1, BL0, BL1, G0, G1)           \
    do {                                                       \
        mma16816(acc[2*(G0)+0], AH, BH0[0], BH0[1]);           \
        mma16816(acc[2*(G0)+1], AH, BH0[2], BH0[3]);           \
        mma16816(acc[2*(G1)+0], AH, BH1[0], BH1[1]);           \
        mma16816(acc[2*(G1)+1], AH, BH1[2], BH1[3]);           \
        mma16816(acc[2*(G0)+0], AL, BH0[0], BH0[1]);           \
        mma16816(acc[2*(G0)+1], AL, BH0[2], BH0[3]);           \
        mma16816(acc[2*(G1)+0], AL, BH1[0], BH1[1]);           \
        mma16816(acc[2*(G1)+1], AL, BH1[2], BH1[3]);           \
        mma16816(acc[2*(G0)+0], AH, BL0[0], BL0[1]);           \
        mma16816(acc[2*(G0)+1], AH, BL0[2], BL0[3]);           \
        mma16816(acc[2*(G1)+0], AH, BL1[0], BL1[1]);           \
        mma16816(acc[2*(G1)+1], AH, BL1[2], BL1[3]);           \
    } while (0)

// ---------------- main fused kernel ----------------
__global__ void __launch_bounds__(NTHREAD, 2)
caps_hmma_kernel(const float* __restrict__ inp, float* __restrict__ dout, int rows)
{
    extern __shared__ char smem[];
    const uint32_t sb = smem_u32(smem);
    const int tid  = threadIdx.x;
    const int lane = tid & 31;
    const int w    = tid >> 5;
    const int rowBase = blockIdx.x * BM;

    // warp tiling: 4 M-groups x 2 N-groups, warp tile 16x80
    const int m0 = (w >> 1) * 16;
    const int n0 = (w & 1) * 80;

    // ldmatrix per-lane offsets (bytes), rows stride 80B
    const int rA = (lane & 7) + ((lane >> 3) & 1) * 8;
    const int cA = (lane >> 4) * 16;
    const int aoff = (m0 + rA) * 80 + cA;

    const int rB = (lane & 7) + ((lane >> 4) ? 8 : 0);
    const int cB = ((lane >> 3) & 1) * 16;
    const int boff = (n0 + rB) * 80 + cB;

    float acc[10][4];
    #pragma unroll
    for (int j = 0; j < 10; ++j)
        #pragma unroll
        for (int e = 0; e < 4; ++e) acc[j][e] = 0.0f;

    // A global-load mapping: 2 float4 per thread per chunk (64 rows x 32 fp32)
    const int arow = tid >> 2;           // 0..63
    const int aseg = tid & 3;            // float4 segs: aseg and aseg+4

    // ---- prologue: fill stage 0 with chunk 0 ----
    {
        char* st = smem;
        #pragma unroll
        for (int i = 0; i < 2; ++i) {
            const int seg = aseg + 4 * i;
            float4 v = *reinterpret_cast<const float4*>(
                inp + (size_t)(rowBase + arow) * K_DIM + seg * 4);
            uint2 hp = make_uint2(pack_bf2(v.x, v.y), pack_bf2(v.z, v.w));
            float lx = v.x - __bfloat162float(__float2bfloat16(v.x));
            float ly = v.y - __bfloat162float(__float2bfloat16(v.y));
            float lz = v.z - __bfloat162float(__float2bfloat16(v.z));
            float lw = v.w - __bfloat162float(__float2bfloat16(v.w));
            uint2 lp = make_uint2(pack_bf2(lx, ly), pack_bf2(lz, lw));
            *reinterpret_cast<uint2*>(st + A_HI + arow * 80 + seg * 8) = hp;
            *reinterpret_cast<uint2*>(st + A_LO + arow * 80 + seg * 8) = lp;
        }
        #pragma unroll
        for (int i = 0; i < 5; ++i) {
            const int u = tid + 256 * i;          // 0..1279
            const int isLo = (u >= 640);
            const int r = isLo ? (u - 640) : u;
            const int n = r >> 2, seg = r & 3;
            const __nv_bfloat16* src = (isLo ? g_Wt_lo : g_Wt_hi) +
                                       (size_t)n * K_DIM + seg * 8;
            cp_async16(sb + (isLo ? B_LO : B_HI) + n * 80 + seg * 16, src);
        }
        CP_COMMIT();
        CP_WAIT0();
    }
    __syncthreads();

    // ---- main loop ----
    for (int c = 0; c < NCHUNK; ++c) {
        const int s = c & 1;
        const uint32_t cur = sb + s * STAGE_BYTES;
        const uint32_t nxt = sb + (s ^ 1) * STAGE_BYTES;
        char* nxtp = smem + (s ^ 1) * STAGE_BYTES;

        float4 ra[2];
        if (c + 1 < NCHUNK) {
            const int kbase = (c + 1) * BK;
            #pragma unroll
            for (int i = 0; i < 2; ++i)
                ra[i] = *reinterpret_cast<const float4*>(
                    inp + (size_t)(rowBase + arow) * K_DIM + kbase + (aseg + 4 * i) * 4);
            #pragma unroll
            for (int i = 0; i < 5; ++i) {
                const int u = tid + 256 * i;
                const int isLo = (u >= 640);
                const int r = isLo ? (u - 640) : u;
                const int n = r >> 2, seg = r & 3;
                const __nv_bfloat16* src = (isLo ? g_Wt_lo : g_Wt_hi) +
                                           (size_t)n * K_DIM + kbase + seg * 8;
                cp_async16(nxt + (isLo ? B_LO : B_HI) + n * 80 + seg * 16, src);
            }
            CP_COMMIT();
        }

        // ---- compute chunk c ----
        const uint32_t ah_base = cur + A_HI + aoff;
        const uint32_t al_base = cur + A_LO + aoff;
        const uint32_t bh_base = cur + B_HI + boff;
        const uint32_t bl_base = cur + B_LO + boff;
        #pragma unroll
        for (int ks = 0; ks < 2; ++ks) {
            uint32_t ah[4], al[4];
            ldsm4(ah, ah_base + ks * 32);
            ldsm4(al, al_base + ks * 32);

            {
                uint32_t bh0[4], bh1[4], bl0[4], bl1[4];
                ldsm4(bh0, bh_base + 0 * 1280 + ks * 32);
                ldsm4(bh1, bh_base + 1 * 1280 + ks * 32);
                ldsm4(bl0, bl_base + 0 * 1280 + ks * 32);
                ldsm4(bl1, bl_base + 1 * 1280 + ks * 32);
                MMA_PAIR(ah, al, bh0, bh1, bl0, bl1, 0, 1);
            }
            {
                uint32_t bh0[4], bh1[4], bl0[4], bl1[4];
                ldsm4(bh0, bh_base + 2 * 1280 + ks * 32);
                ldsm4(bh1, bh_base + 3 * 1280 + ks * 32);
                ldsm4(bl0, bl_base + 2 * 1280 + ks * 32);
                ldsm4(bl1, bl_base + 3 * 1280 + ks * 32);
                MMA_PAIR(ah, al, bh0, bh1, bl0, bl1, 2, 3);
            }
            {
                uint32_t bh0[4], bl0[4];
                ldsm4(bh0, bh_base + 4 * 1280 + ks * 32);
                ldsm4(bl0, bl_base + 4 * 1280 + ks * 32);
                mma16816(acc[8], ah, bh0[0], bh0[1]);
                mma16816(acc[9], ah, bh0[2], bh0[3]);
                mma16816(acc[8], al, bh0[0], bh0[1]);
                mma16816(acc[9], al, bh0[2], bh0[3]);
                mma16816(acc[8], ah, bl0[0], bl0[1]);
                mma16816(acc[9], ah, bl0[2], bl0[3]);
            }
        }

        if (c + 1 < NCHUNK) {
            #pragma unroll
            for (int i = 0; i < 2; ++i) {
                const int seg = aseg + 4 * i;
                float4 v = ra[i];
                uint2 hp = make_uint2(pack_bf2(v.x, v.y), pack_bf2(v.z, v.w));
                float lx = v.x - __bfloat162float(__float2bfloat16(v.x));
                float ly = v.y - __bfloat162float(__float2bfloat16(v.y));
                float lz = v.z - __bfloat162float(__float2bfloat16(v.z));
                float lw = v.w - __bfloat162float(__float2bfloat16(v.w));
                uint2 lp = make_uint2(pack_bf2(lx, ly), pack_bf2(lz, lw));
                *reinterpret_cast<uint2*>(nxtp + A_HI + arow * 80 + seg * 8) = hp;
                *reinterpret_cast<uint2*>(nxtp + A_LO + arow * 80 + seg * 8) = lp;
            }
            CP_WAIT0();
        }
        __syncthreads();
    }

    // ---- write C frags to padded smem hat tile ----
    float* hat = reinterpret_cast<float*>(smem);
    {
        const int r0 = m0 + (lane >> 2);
        const int cbase = n0 + (lane & 3) * 2;
        #pragma unroll
        for (int j = 0; j < 10; ++j) {
            const int col = cbase + 8 * j;
            hat[r0 * HAT_STRIDE + col]           = acc[j][0];
            hat[r0 * HAT_STRIDE + col + 1]       = acc[j][1];
            hat[(r0 + 8) * HAT_STRIDE + col]     = acc[j][2];
            hat[(r0 + 8) * HAT_STRIDE + col + 1] = acc[j][3];
        }
    }
    __syncthreads();

    // ---- dynamic routing: one thread per row ----
    if (tid < BM) {
        const float* h = &hat[tid * HAT_STRIDE];

        float b[NC];
        #pragma unroll
        for (int n = 0; n < NC; ++n) b[n] = 0.0f;
        float out[DC];

        #pragma unroll
        for (int it = 0; it < 3; ++it) {
            float m = b[0];
            #pragma unroll
            for (int n = 1; n < NC; ++n) m = fmaxf(m, b[n]);
            float cc[NC];
            float se = 0.0f;
            #pragma unroll
            for (int n = 0; n < NC; ++n) { cc[n] = expf(b[n] - m); se += cc[n]; }
            const float inv = 1.0f / se;

            float s[DC];
            #pragma unroll
            for (int d = 0; d < DC; ++d) s[d] = 0.0f;
            #pragma unroll
            for (int n = 0; n < NC; ++n) {
                const float cn = cc[n] * inv;
                #pragma unroll
                for (int d = 0; d < DC; ++d)
                    s[d] = fmaf(cn, h[n * DC + d], s[d]);
            }

            float s2 = 0.0f;
            #pragma unroll
            for (int d = 0; d < DC; ++d) s2 = fmaf(s[d], s[d], s2);
            const float scale = s2 / ((1.0f + s2) * sqrtf(s2 + 1e-7f));
            #pragma unroll
            for (int d = 0; d < DC; ++d) out[d] = scale * s[d];

            if (it < 2) {
                #pragma unroll
                for (int n = 0; n < NC; ++n) {
                    float dot = 0.0f;
                    #pragma unroll
                    for (int d = 0; d < DC; ++d)
                        dot = fmaf(h[n * DC + d], out[d], dot);
                    b[n] += dot;
                }
            }
        }

        float4* o = reinterpret_cast<float4*>(dout + (size_t)(rowBase + tid) * DC);
        o[0] = make_float4(out[0],  out[1],  out[2],  out[3]);
        o[1] = make_float4(out[4],  out[5],  out[6],  out[7]);
        o[2] = make_float4(out[8],  out[9],  out[10], out[11]);
        o[3] = make_float4(out[12], out[13], out[14], out[15]);
    }
}

extern "C" void kernel_launch(void* const* d_in, const int* in_sizes, int n_in,
                              void* d_out, int out_size)
{
    const float* inp = (const float*)d_in[0];
    const float* wk  = (const float*)d_in[1];
    float* out       = (float*)d_out;

    const int rows = in_sizes[0] / K_DIM;   // 16384

    wt_split_kernel<<<(N_DIM * K_DIM + 255) / 256, 256>>>(wk);

    cudaFuncSetAttribute(caps_hmma_kernel,
                         cudaFuncAttributeMaxDynamicSharedMemorySize, SMEM_TOTAL);
    caps_hmma_kernel<<<rows / BM, NTHREAD, SMEM_TOTAL>>>(inp, out, rows);
}

// round 6
// speedup vs baseline: 1.0458x; 1.0458x over previous
#include <cuda_runtime.h>
#include <cuda_bf16.h>
#include <math.h>
#include <stdint.h>

#define K_DIM   2048
#define N_DIM   160
#define NC      10
#define DC      16
#define BM      64
#define BK      32
#define NCHUNK  (K_DIM / BK)          // 64
#define NTHREAD 128
#define HAT_STRIDE 165

// stage layout (bytes), rows padded to 80B for conflict-free ldmatrix
#define A_HI    0
#define A_LO    5120
#define B_HI    10240
#define B_LO    23040
#define STAGE_BYTES 35840
#define SMEM_TOTAL  (2 * STAGE_BYTES)   // 71680; hat tile 64*165*4=42240 fits

// Precomputed transposed split weights: Wt[n][k] = W[k][n]
__device__ __nv_bfloat16 g_Wt_hi[N_DIM * K_DIM];
__device__ __nv_bfloat16 g_Wt_lo[N_DIM * K_DIM];

// ---------------- helpers ----------------
__device__ __forceinline__ uint32_t smem_u32(const void* p) {
    uint32_t a;
    asm("{ .reg .u64 t; cvta.to.shared.u64 t, %1; cvt.u32.u64 %0, t; }" : "=r"(a) : "l"(p));
    return a;
}
__device__ __forceinline__ void ldsm4(uint32_t* d, uint32_t addr) {
    asm volatile("ldmatrix.sync.aligned.m8n8.x4.shared.b16 {%0,%1,%2,%3}, [%4];"
                 : "=r"(d[0]), "=r"(d[1]), "=r"(d[2]), "=r"(d[3]) : "r"(addr));
}
__device__ __forceinline__ void mma16816(float* c, const uint32_t* a,
                                         uint32_t b0, uint32_t b1) {
    asm volatile("mma.sync.aligned.m16n8k16.row.col.f32.bf16.bf16.f32 "
                 "{%0,%1,%2,%3}, {%4,%5,%6,%7}, {%8,%9}, {%0,%1,%2,%3};"
                 : "+f"(c[0]), "+f"(c[1]), "+f"(c[2]), "+f"(c[3])
                 : "r"(a[0]), "r"(a[1]), "r"(a[2]), "r"(a[3]), "r"(b0), "r"(b1));
}
__device__ __forceinline__ void cp_async16(uint32_t smem_dst, const void* gsrc) {
    asm volatile("cp.async.cg.shared.global [%0], [%1], 16;"
                 :: "r"(smem_dst), "l"(__cvta_generic_to_global(gsrc)) : "memory");
}
#define CP_COMMIT() asm volatile("cp.async.commit_group;" ::: "memory")
#define CP_WAIT0()  asm volatile("cp.async.wait_group 0;" ::: "memory")

__device__ __forceinline__ uint32_t pack_bf2(float x, float y) {
    __nv_bfloat162 t = __floats2bfloat162_rn(x, y);
    return *reinterpret_cast<uint32_t*>(&t);
}

// ---------------- pre-kernel: split + transpose W ----------------
__global__ void wt_split_kernel(const float* __restrict__ wk) {
    int idx = blockIdx.x * 256 + threadIdx.x;
    if (idx < N_DIM * K_DIM) {
        int n = idx / K_DIM;
        int k = idx % K_DIM;
        float v = wk[(size_t)k * N_DIM + n];
        __nv_bfloat16 hi = __float2bfloat16(v);
        g_Wt_hi[idx] = hi;
        g_Wt_lo[idx] = __float2bfloat16(v - __bfloat162float(hi));
    }
}

// 24 MMAs, term-major: same-accumulator RAW distance = 8
#define MMA_BLOCK(AH, AL, BH0, BH1, BL0, BL1, ACCBASE)                       \
    do {                                                                     \
        mma16816(acc[0][(ACCBASE) + 0], AH[0], BH0[0], BH0[1]);              \
        mma16816(acc[1][(ACCBASE) + 0], AH[1], BH0[0], BH0[1]);              \
        mma16816(acc[0][(ACCBASE) + 1], AH[0], BH0[2], BH0[3]);              \
        mma16816(acc[1][(ACCBASE) + 1], AH[1], BH0[2], BH0[3]);              \
        mma16816(acc[0][(ACCBASE) + 2], AH[0], BH1[0], BH1[1]);              \
        mma16816(acc[1][(ACCBASE) + 2], AH[1], BH1[0], BH1[1]);              \
        mma16816(acc[0][(ACCBASE) + 3], AH[0], BH1[2], BH1[3]);              \
        mma16816(acc[1][(ACCBASE) + 3], AH[1], BH1[2], BH1[3]);              \
        mma16816(acc[0][(ACCBASE) + 0], AL[0], BH0[0], BH0[1]);              \
        mma16816(acc[1][(ACCBASE) + 0], AL[1], BH0[0], BH0[1]);              \
        mma16816(acc[0][(ACCBASE) + 1], AL[0], BH0[2], BH0[3]);              \
        mma16816(acc[1][(ACCBASE) + 1], AL[1], BH0[2], BH0[3]);              \
        mma16816(acc[0][(ACCBASE) + 2], AL[0], BH1[0], BH1[1]);              \
        mma16816(acc[1][(ACCBASE) + 2], AL[1], BH1[0], BH1[1]);              \
        mma16816(acc[0][(ACCBASE) + 3], AL[0], BH1[2], BH1[3]);              \
        mma16816(acc[1][(ACCBASE) + 3], AL[1], BH1[2], BH1[3]);              \
        mma16816(acc[0][(ACCBASE) + 0], AH[0], BL0[0], BL0[1]);              \
        mma16816(acc[1][(ACCBASE) + 0], AH[1], BL0[0], BL0[1]);              \
        mma16816(acc[0][(ACCBASE) + 1], AH[0], BL0[2], BL0[3]);              \
        mma16816(acc[1][(ACCBASE) + 1], AH[1], BL0[2], BL0[3]);              \
        mma16816(acc[0][(ACCBASE) + 2], AH[0], BL1[0], BL1[1]);              \
        mma16816(acc[1][(ACCBASE) + 2], AH[1], BL1[0], BL1[1]);              \
        mma16816(acc[0][(ACCBASE) + 3], AH[0], BL1[2], BL1[3]);              \
        mma16816(acc[1][(ACCBASE) + 3], AH[1], BL1[2], BL1[3]);              \
    } while (0)

// ---------------- main fused kernel ----------------
__global__ void __launch_bounds__(NTHREAD, 2)
caps_hmma_kernel(const float* __restrict__ inp, float* __restrict__ dout, int rows)
{
    extern __shared__ char smem[];
    const uint32_t sb = smem_u32(smem);
    const int tid  = threadIdx.x;
    const int lane = tid & 31;
    const int w    = tid >> 5;
    const int rowBase = blockIdx.x * BM;

    // 4 warps: 2 M-groups x 2 N-groups, warp tile 32x80
    const int m0 = (w >> 1) * 32;
    const int n0 = (w & 1) * 80;

    // ldmatrix per-lane offsets (bytes), rows stride 80B
    const int rA = (lane & 7) + ((lane >> 3) & 1) * 8;
    const int cA = (lane >> 4) * 16;
    const int aoff = (m0 + rA) * 80 + cA;

    const int rB = (lane & 7) + ((lane >> 4) ? 8 : 0);
    const int cB = ((lane >> 3) & 1) * 16;
    const int boff = (n0 + rB) * 80 + cB;

    float acc[2][10][4];
    #pragma unroll
    for (int mt = 0; mt < 2; ++mt)
        #pragma unroll
        for (int j = 0; j < 10; ++j)
            #pragma unroll
            for (int e = 0; e < 4; ++e) acc[mt][j][e] = 0.0f;

    // A global-load mapping: 4 float4 per thread per chunk (64 rows x 32 fp32, 128 thr)
    const int arow = tid >> 1;            // 0..63
    const int aseg0 = (tid & 1) * 4;      // float4 segs aseg0..aseg0+3

    // ---- prologue: fill stage 0 with chunk 0 ----
    {
        char* st = smem;
        #pragma unroll
        for (int j = 0; j < 4; ++j) {
            const int seg = aseg0 + j;
            float4 v = *reinterpret_cast<const float4*>(
                inp + (size_t)(rowBase + arow) * K_DIM + seg * 4);
            uint2 hp = make_uint2(pack_bf2(v.x, v.y), pack_bf2(v.z, v.w));
            float lx = v.x - __bfloat162float(__float2bfloat16(v.x));
            float ly = v.y - __bfloat162float(__float2bfloat16(v.y));
            float lz = v.z - __bfloat162float(__float2bfloat16(v.z));
            float lw = v.w - __bfloat162float(__float2bfloat16(v.w));
            uint2 lp = make_uint2(pack_bf2(lx, ly), pack_bf2(lz, lw));
            *reinterpret_cast<uint2*>(st + A_HI + arow * 80 + seg * 8) = hp;
            *reinterpret_cast<uint2*>(st + A_LO + arow * 80 + seg * 8) = lp;
        }
        #pragma unroll
        for (int i = 0; i < 10; ++i) {
            const int u = tid + 128 * i;          // 0..1279
            const int isLo = (u >= 640);
            const int r = isLo ? (u - 640) : u;
            const int n = r >> 2, seg = r & 3;
            const __nv_bfloat16* src = (isLo ? g_Wt_lo : g_Wt_hi) +
                                       (size_t)n * K_DIM + seg * 8;
            cp_async16(sb + (isLo ? B_LO : B_HI) + n * 80 + seg * 16, src);
        }
        CP_COMMIT();
        CP_WAIT0();
    }
    __syncthreads();

    // ---- main loop ----
    for (int c = 0; c < NCHUNK; ++c) {
        const int s = c & 1;
        const uint32_t cur = sb + s * STAGE_BYTES;
        const uint32_t nxt = sb + (s ^ 1) * STAGE_BYTES;
        char* nxtp = smem + (s ^ 1) * STAGE_BYTES;

        float4 ra[4];
        if (c + 1 < NCHUNK) {
            const int kbase = (c + 1) * BK;
            #pragma unroll
            for (int j = 0; j < 4; ++j)
                ra[j] = *reinterpret_cast<const float4*>(
                    inp + (size_t)(rowBase + arow) * K_DIM + kbase + (aseg0 + j) * 4);
            #pragma unroll
            for (int i = 0; i < 10; ++i) {
                const int u = tid + 128 * i;
                const int isLo = (u >= 640);
                const int r = isLo ? (u - 640) : u;
                const int n = r >> 2, seg = r & 3;
                const __nv_bfloat16* src = (isLo ? g_Wt_lo : g_Wt_hi) +
                                           (size_t)n * K_DIM + kbase + seg * 8;
                cp_async16(nxt + (isLo ? B_LO : B_HI) + n * 80 + seg * 16, src);
            }
            CP_COMMIT();
        }

        // ---- compute chunk c ----
        const uint32_t ah_base = cur + A_HI + aoff;
        const uint32_t al_base = cur + A_LO + aoff;
        const uint32_t bh_base = cur + B_HI + boff;
        const uint32_t bl_base = cur + B_LO + boff;
        #pragma unroll
        for (int ks = 0; ks < 2; ++ks) {
            uint32_t ah[2][4], al[2][4];
            ldsm4(ah[0], ah_base + ks * 32);
            ldsm4(ah[1], ah_base + 16 * 80 + ks * 32);
            ldsm4(al[0], al_base + ks * 32);
            ldsm4(al[1], al_base + 16 * 80 + ks * 32);

            {
                uint32_t bh0[4], bh1[4], bl0[4], bl1[4];
                ldsm4(bh0, bh_base + 0 * 1280 + ks * 32);
                ldsm4(bh1, bh_base + 1 * 1280 + ks * 32);
                ldsm4(bl0, bl_base + 0 * 1280 + ks * 32);
                ldsm4(bl1, bl_base + 1 * 1280 + ks * 32);
                MMA_BLOCK(ah, al, bh0, bh1, bl0, bl1, 0);
            }
            {
                uint32_t bh0[4], bh1[4], bl0[4], bl1[4];
                ldsm4(bh0, bh_base + 2 * 1280 + ks * 32);
                ldsm4(bh1, bh_base + 3 * 1280 + ks * 32);
                ldsm4(bl0, bl_base + 2 * 1280 + ks * 32);
                ldsm4(bl1, bl_base + 3 * 1280 + ks * 32);
                MMA_BLOCK(ah, al, bh0, bh1, bl0, bl1, 4);
            }
            {
                uint32_t bh0[4], bl0[4];
                ldsm4(bh0, bh_base + 4 * 1280 + ks * 32);
                ldsm4(bl0, bl_base + 4 * 1280 + ks * 32);
                mma16816(acc[0][8], ah[0], bh0[0], bh0[1]);
                mma16816(acc[1][8], ah[1], bh0[0], bh0[1]);
                mma16816(acc[0][9], ah[0], bh0[2], bh0[3]);
                mma16816(acc[1][9], ah[1], bh0[2], bh0[3]);
                mma16816(acc[0][8], al[0], bh0[0], bh0[1]);
                mma16816(acc[1][8], al[1], bh0[0], bh0[1]);
                mma16816(acc[0][9], al[0], bh0[2], bh0[3]);
                mma16816(acc[1][9], al[1], bh0[2], bh0[3]);
                mma16816(acc[0][8], ah[0], bl0[0], bl0[1]);
                mma16816(acc[1][8], ah[1], bl0[0], bl0[1]);
                mma16816(acc[0][9], ah[0], bl0[2], bl0[3]);
                mma16816(acc[1][9], ah[1], bl0[2], bl0[3]);
            }
        }

        if (c + 1 < NCHUNK) {
            #pragma unroll
            for (int j = 0; j < 4; ++j) {
                const int seg = aseg0 + j;
                float4 v = ra[j];
                uint2 hp = make_uint2(pack_bf2(v.x, v.y), pack_bf2(v.z, v.w));
                float lx = v.x - __bfloat162float(__float2bfloat16(v.x));
                float ly = v.y - __bfloat162float(__float2bfloat16(v.y));
                float lz = v.z - __bfloat162float(__float2bfloat16(v.z));
                float lw = v.w - __bfloat162float(__float2bfloat16(v.w));
                uint2 lp = make_uint2(pack_bf2(lx, ly), pack_bf2(lz, lw));
                *reinterpret_cast<uint2*>(nxtp + A_HI + arow * 80 + seg * 8) = hp;
                *reinterpret_cast<uint2*>(nxtp + A_LO + arow * 80 + seg * 8) = lp;
            }
            CP_WAIT0();
        }
        __syncthreads();
    }

    // ---- write C frags to padded smem hat tile ----
    float* hat = reinterpret_cast<float*>(smem);
    {
        const int cbase = n0 + (lane & 3) * 2;
        #pragma unroll
        for (int mt = 0; mt < 2; ++mt) {
            const int r0 = m0 + mt * 16 + (lane >> 2);
            #pragma unroll
            for (int j = 0; j < 10; ++j) {
                const int col = cbase + 8 * j;
                hat[r0 * HAT_STRIDE + col]           = acc[mt][j][0];
                hat[r0 * HAT_STRIDE + col + 1]       = acc[mt][j][1];
                hat[(r0 + 8) * HAT_STRIDE + col]     = acc[mt][j][2];
                hat[(r0 + 8) * HAT_STRIDE + col + 1] = acc[mt][j][3];
            }
        }
    }
    __syncthreads();

    // ---- dynamic routing: one thread per row ----
    if (tid < BM) {
        const float* h = &hat[tid * HAT_STRIDE];

        float b[NC];
        #pragma unroll
        for (int n = 0; n < NC; ++n) b[n] = 0.0f;
        float out[DC];

        #pragma unroll
        for (int it = 0; it < 3; ++it) {
            float m = b[0];
            #pragma unroll
            for (int n = 1; n < NC; ++n) m = fmaxf(m, b[n]);
            float cc[NC];
            float se = 0.0f;
            #pragma unroll
            for (int n = 0; n < NC; ++n) { cc[n] = expf(b[n] - m); se += cc[n]; }
            const float inv = 1.0f / se;

            float s[DC];
            #pragma unroll
            for (int d = 0; d < DC; ++d) s[d] = 0.0f;
            #pragma unroll
            for (int n = 0; n < NC; ++n) {
                const float cn = cc[n] * inv;
                #pragma unroll
                for (int d = 0; d < DC; ++d)
                    s[d] = fmaf(cn, h[n * DC + d], s[d]);
            }

            float s2 = 0.0f;
            #pragma unroll
            for (int d = 0; d < DC; ++d) s2 = fmaf(s[d], s[d], s2);
            const float scale = s2 / ((1.0f + s2) * sqrtf(s2 + 1e-7f));
            #pragma unroll
            for (int d = 0; d < DC; ++d) out[d] = scale * s[d];

            if (it < 2) {
                #pragma unroll
                for (int n = 0; n < NC; ++n) {
                    float dot = 0.0f;
                    #pragma unroll
                    for (int d = 0; d < DC; ++d)
                        dot = fmaf(h[n * DC + d], out[d], dot);
                    b[n] += dot;
                }
            }
        }

        float4* o = reinterpret_cast<float4*>(dout + (size_t)(rowBase + tid) * DC);
        o[0] = make_float4(out[0],  out[1],  out[2],  out[3]);
        o[1] = make_float4(out[4],  out[5],  out[6],  out[7]);
        o[2] = make_float4(out[8],  out[9],  out[10], out[11]);
        o[3] = make_float4(out[12], out[13], out[14], out[15]);
    }
}

extern "C" void kernel_launch(void* const* d_in, const int* in_sizes, int n_in,
                              void* d_out, int out_size)
{
    const float* inp = (const float*)d_in[0];
    const float* wk  = (const float*)d_in[1];
    float* out       = (float*)d_out;

    const int rows = in_sizes[0] / K_DIM;   // 16384

    wt_split_kernel<<<(N_DIM * K_DIM + 255) / 256, 256>>>(wk);

    cudaFuncSetAttribute(caps_hmma_kernel,
                         cudaFuncAttributeMaxDynamicSharedMemorySize, SMEM_TOTAL);
    caps_hmma_kernel<<<rows / BM, NTHREAD, SMEM_TOTAL>>>(inp, out, rows);
}

// round 7
// speedup vs baseline: 1.0818x; 1.0345x over previous
#include <cuda_runtime.h>
#include <cuda_bf16.h>
#include <math.h>
#include <stdint.h>

#define K_DIM   2048
#define N_DIM   160
#define NC      10
#define DC      16
#define BM      64
#define BK      64
#define NCHUNK  (K_DIM / BK)          // 32
#define NTHREAD 256
#define HAT_STRIDE 165

// rows padded to 144B (128+16): r*144 mod 128 = 16r -> conflict-free ldmatrix
#define ROWB    144
// smem layout (bytes)
#define A_HI    0
#define A_LO    (64 * ROWB)               // 9216
#define B_BASE  (2 * 64 * ROWB)           // 18432
#define B_HALF  (160 * ROWB)              // 23040 (hi or lo)
#define B_STAGE (2 * B_HALF)              // 46080
#define SMEM_TOTAL (B_BASE + 2 * B_STAGE) // 110592

// Precomputed transposed split weights: Wt[n][k] = W[k][n]
__device__ __nv_bfloat16 g_Wt_hi[N_DIM * K_DIM];
__device__ __nv_bfloat16 g_Wt_lo[N_DIM * K_DIM];

// ---------------- helpers ----------------
__device__ __forceinline__ uint32_t smem_u32(const void* p) {
    uint32_t a;
    asm("{ .reg .u64 t; cvta.to.shared.u64 t, %1; cvt.u32.u64 %0, t; }" : "=r"(a) : "l"(p));
    return a;
}
__device__ __forceinline__ void ldsm4(uint32_t* d, uint32_t addr) {
    asm volatile("ldmatrix.sync.aligned.m8n8.x4.shared.b16 {%0,%1,%2,%3}, [%4];"
                 : "=r"(d[0]), "=r"(d[1]), "=r"(d[2]), "=r"(d[3]) : "r"(addr));
}
__device__ __forceinline__ void mma16816(float* c, const uint32_t* a,
                                         uint32_t b0, uint32_t b1) {
    asm volatile("mma.sync.aligned.m16n8k16.row.col.f32.bf16.bf16.f32 "
                 "{%0,%1,%2,%3}, {%4,%5,%6,%7}, {%8,%9}, {%0,%1,%2,%3};"
                 : "+f"(c[0]), "+f"(c[1]), "+f"(c[2]), "+f"(c[3])
                 : "r"(a[0]), "r"(a[1]), "r"(a[2]), "r"(a[3]), "r"(b0), "r"(b1));
}
__device__ __forceinline__ void cp_async16(uint32_t smem_dst, const void* gsrc) {
    asm volatile("cp.async.cg.shared.global [%0], [%1], 16;"
                 :: "r"(smem_dst), "l"(__cvta_generic_to_global(gsrc)) : "memory");
}
#define CP_COMMIT() asm volatile("cp.async.commit_group;" ::: "memory")
#define CP_WAIT0()  asm volatile("cp.async.wait_group 0;" ::: "memory")

__device__ __forceinline__ uint32_t pack_bf2(float x, float y) {
    __nv_bfloat162 t = __floats2bfloat162_rn(x, y);
    return *reinterpret_cast<uint32_t*>(&t);
}

// ---------------- pre-kernel: split + transpose W ----------------
__global__ void wt_split_kernel(const float* __restrict__ wk) {
    int idx = blockIdx.x * 256 + threadIdx.x;
    if (idx < N_DIM * K_DIM) {
        int n = idx / K_DIM;
        int k = idx % K_DIM;
        float v = wk[(size_t)k * N_DIM + n];
        __nv_bfloat16 hi = __float2bfloat16(v);
        g_Wt_hi[idx] = hi;
        g_Wt_lo[idx] = __float2bfloat16(v - __bfloat162float(hi));
    }
}

// 12 MMAs term-major over a pair of B groups: same-acc RAW distance = 4
#define MMA_PAIR(AH, AL, BH0, BH1, BL0, BL1, G0, G1)           \
    do {                                                       \
        mma16816(acc[2*(G0)+0], AH, BH0[0], BH0[1]);           \
        mma16816(acc[2*(G0)+1], AH, BH0[2], BH0[3]);           \
        mma16816(acc[2*(G1)+0], AH, BH1[0], BH1[1]);           \
        mma16816(acc[2*(G1)+1], AH, BH1[2], BH1[3]);           \
        mma16816(acc[2*(G0)+0], AL, BH0[0], BH0[1]);           \
        mma16816(acc[2*(G0)+1], AL, BH0[2], BH0[3]);           \
        mma16816(acc[2*(G1)+0], AL, BH1[0], BH1[1]);           \
        mma16816(acc[2*(G1)+1], AL, BH1[2], BH1[3]);           \
        mma16816(acc[2*(G0)+0], AH, BL0[0], BL0[1]);           \
        mma16816(acc[2*(G0)+1], AH, BL0[2], BL0[3]);           \
        mma16816(acc[2*(G1)+0], AH, BL1[0], BL1[1]);           \
        mma16816(acc[2*(G1)+1], AH, BL1[2], BL1[3]);           \
    } while (0)

// ---------------- main fused kernel ----------------
__global__ void __launch_bounds__(NTHREAD, 2)
caps_hmma_kernel(const float* __restrict__ inp, float* __restrict__ dout, int rows)
{
    extern __shared__ char smem[];
    const uint32_t sb = smem_u32(smem);
    const int tid  = threadIdx.x;
    const int lane = tid & 31;
    const int w    = tid >> 5;
    const int rowBase = blockIdx.x * BM;

    // 8 warps: 4 M-groups x 2 N-groups, warp tile 16x80
    const int m0 = (w >> 1) * 16;
    const int n0 = (w & 1) * 80;

    // ldmatrix per-lane offsets (bytes), row stride 144B
    const int rA = (lane & 7) + ((lane >> 3) & 1) * 8;
    const int cA = (lane >> 4) * 16;
    const int aoff = (m0 + rA) * ROWB + cA;

    const int rB = (lane & 7) + ((lane >> 4) ? 8 : 0);
    const int cB = ((lane >> 3) & 1) * 16;
    const int boff = (n0 + rB) * ROWB + cB;

    float acc[10][4];
    #pragma unroll
    for (int j = 0; j < 10; ++j)
        #pragma unroll
        for (int e = 0; e < 4; ++e) acc[j][e] = 0.0f;

    // A global-load mapping: 64 rows x 64 fp32 = 1024 float4; 4/thread
    const int arow = tid >> 2;            // 0..63
    const int aseg0 = tid & 3;            // segs aseg0 + 4j

    // ---- prologue: A(0) + B(0) into stage 0 ----
    {
        #pragma unroll
        for (int j = 0; j < 4; ++j) {
            const int seg = aseg0 + 4 * j;
            float4 v = *reinterpret_cast<const float4*>(
                inp + (size_t)(rowBase + arow) * K_DIM + seg * 4);
            uint2 hp = make_uint2(pack_bf2(v.x, v.y), pack_bf2(v.z, v.w));
            float lx = v.x - __bfloat162float(__float2bfloat16(v.x));
            float ly = v.y - __bfloat162float(__float2bfloat16(v.y));
            float lz = v.z - __bfloat162float(__float2bfloat16(v.z));
            float lw = v.w - __bfloat162float(__float2bfloat16(v.w));
            uint2 lp = make_uint2(pack_bf2(lx, ly), pack_bf2(lz, lw));
            *reinterpret_cast<uint2*>(smem + A_HI + arow * ROWB + seg * 8) = hp;
            *reinterpret_cast<uint2*>(smem + A_LO + arow * ROWB + seg * 8) = lp;
        }
        // B(0): 2560 16B segs (hi 1280 + lo 1280), 10 per thread
        #pragma unroll
        for (int i = 0; i < 10; ++i) {
            const int u = tid + 256 * i;
            const int isLo = (u >= 1280);
            const int r = isLo ? (u - 1280) : u;
            const int n = r >> 3, seg = r & 7;
            const __nv_bfloat16* src = (isLo ? g_Wt_lo : g_Wt_hi) +
                                       (size_t)n * K_DIM + seg * 8;
            cp_async16(sb + B_BASE + (isLo ? B_HALF : 0) + n * ROWB + seg * 16, src);
        }
        CP_COMMIT();
        CP_WAIT0();
    }
    __syncthreads();

    // ---- main loop: A single-stage (reg prefetch), B double-buffered ----
    for (int c = 0; c < NCHUNK; ++c) {
        const uint32_t bcur = sb + B_BASE + (c & 1) * B_STAGE;
        const int has_next = (c + 1) < NCHUNK;

        float4 ra[4];
        if (has_next) {
            const int kbase = (c + 1) * BK;
            // B(c+1) -> other B stage, straight from global
            const uint32_t bnxt = sb + B_BASE + ((c + 1) & 1) * B_STAGE;
            #pragma unroll
            for (int i = 0; i < 10; ++i) {
                const int u = tid + 256 * i;
                const int isLo = (u >= 1280);
                const int r = isLo ? (u - 1280) : u;
                const int n = r >> 3, seg = r & 7;
                const __nv_bfloat16* src = (isLo ? g_Wt_lo : g_Wt_hi) +
                                           (size_t)n * K_DIM + kbase + seg * 8;
                cp_async16(bnxt + (isLo ? B_HALF : 0) + n * ROWB + seg * 16, src);
            }
            CP_COMMIT();
            // A(c+1) -> registers
            #pragma unroll
            for (int j = 0; j < 4; ++j)
                ra[j] = *reinterpret_cast<const float4*>(
                    inp + (size_t)(rowBase + arow) * K_DIM + kbase + (aseg0 + 4 * j) * 4);
        }

        // ---- compute chunk c: 4 K-steps ----
        const uint32_t ah_base = sb + A_HI + aoff;
        const uint32_t al_base = sb + A_LO + aoff;
        const uint32_t bh_base = bcur + boff;
        const uint32_t bl_base = bcur + B_HALF + boff;
        #pragma unroll
        for (int ks = 0; ks < 4; ++ks) {
            uint32_t ah[4], al[4];
            ldsm4(ah, ah_base + ks * 32);
            ldsm4(al, al_base + ks * 32);
            {
                uint32_t bh0[4], bh1[4], bl0[4], bl1[4];
                ldsm4(bh0, bh_base + 0 * 16 * ROWB + ks * 32);
                ldsm4(bh1, bh_base + 1 * 16 * ROWB + ks * 32);
                ldsm4(bl0, bl_base + 0 * 16 * ROWB + ks * 32);
                ldsm4(bl1, bl_base + 1 * 16 * ROWB + ks * 32);
                MMA_PAIR(ah, al, bh0, bh1, bl0, bl1, 0, 1);
            }
            {
                uint32_t bh0[4], bh1[4], bl0[4], bl1[4];
                ldsm4(bh0, bh_base + 2 * 16 * ROWB + ks * 32);
                ldsm4(bh1, bh_base + 3 * 16 * ROWB + ks * 32);
                ldsm4(bl0, bl_base + 2 * 16 * ROWB + ks * 32);
                ldsm4(bl1, bl_base + 3 * 16 * ROWB + ks * 32);
                MMA_PAIR(ah, al, bh0, bh1, bl0, bl1, 2, 3);
            }
            {
                uint32_t bh0[4], bl0[4];
                ldsm4(bh0, bh_base + 4 * 16 * ROWB + ks * 32);
                ldsm4(bl0, bl_base + 4 * 16 * ROWB + ks * 32);
                mma16816(acc[8], ah, bh0[0], bh0[1]);
                mma16816(acc[9], ah, bh0[2], bh0[3]);
                mma16816(acc[8], al, bh0[0], bh0[1]);
                mma16816(acc[9], al, bh0[2], bh0[3]);
                mma16816(acc[8], ah, bl0[0], bl0[1]);
                mma16816(acc[9], ah, bl0[2], bl0[3]);
            }
        }

        __syncthreads();   // everyone done reading A stage

        if (has_next) {
            // split + STS A(c+1) into the single A stage
            #pragma unroll
            for (int j = 0; j < 4; ++j) {
                const int seg = aseg0 + 4 * j;
                float4 v = ra[j];
                uint2 hp = make_uint2(pack_bf2(v.x, v.y), pack_bf2(v.z, v.w));
                float lx = v.x - __bfloat162float(__float2bfloat16(v.x));
                float ly = v.y - __bfloat162float(__float2bfloat16(v.y));
                float lz = v.z - __bfloat162float(__float2bfloat16(v.z));
                float lw = v.w - __bfloat162float(__float2bfloat16(v.w));
                uint2 lp = make_uint2(pack_bf2(lx, ly), pack_bf2(lz, lw));
                *reinterpret_cast<uint2*>(smem + A_HI + arow * ROWB + seg * 8) = hp;
                *reinterpret_cast<uint2*>(smem + A_LO + arow * ROWB + seg * 8) = lp;
            }
            CP_WAIT0();        // B(c+1) landed
            __syncthreads();
        }
    }
    __syncthreads();

    // ---- write C frags to padded smem hat tile ----
    float* hat = reinterpret_cast<float*>(smem);
    {
        const int r0 = m0 + (lane >> 2);
        const int cbase = n0 + (lane & 3) * 2;
        #pragma unroll
        for (int j = 0; j < 10; ++j) {
            const int col = cbase + 8 * j;
            hat[r0 * HAT_STRIDE + col]           = acc[j][0];
            hat[r0 * HAT_STRIDE + col + 1]       = acc[j][1];
            hat[(r0 + 8) * HAT_STRIDE + col]     = acc[j][2];
            hat[(r0 + 8) * HAT_STRIDE + col + 1] = acc[j][3];
        }
    }
    __syncthreads();

    // ---- dynamic routing: one thread per row ----
    if (tid < BM) {
        const float* h = &hat[tid * HAT_STRIDE];

        float b[NC];
        #pragma unroll
        for (int n = 0; n < NC; ++n) b[n] = 0.0f;
        float out[DC];

        #pragma unroll
        for (int it = 0; it < 3; ++it) {
            float m = b[0];
            #pragma unroll
            for (int n = 1; n < NC; ++n) m = fmaxf(m, b[n]);
            float cc[NC];
            float se = 0.0f;
            #pragma unroll
            for (int n = 0; n < NC; ++n) { cc[n] = expf(b[n] - m); se += cc[n]; }
            const float inv = 1.0f / se;

            float s[DC];
            #pragma unroll
            for (int d = 0; d < DC; ++d) s[d] = 0.0f;
            #pragma unroll
            for (int n = 0; n < NC; ++n) {
                const float cn = cc[n] * inv;
                #pragma unroll
                for (int d = 0; d < DC; ++d)
                    s[d] = fmaf(cn, h[n * DC + d], s[d]);
            }

            float s2 = 0.0f;
            #pragma unroll
            for (int d = 0; d < DC; ++d) s2 = fmaf(s[d], s[d], s2);
            const float scale = s2 / ((1.0f + s2) * sqrtf(s2 + 1e-7f));
            #pragma unroll
            for (int d = 0; d < DC; ++d) out[d] = scale * s[d];

            if (it < 2) {
                #pragma unroll
                for (int n = 0; n < NC; ++n) {
                    float dot = 0.0f;
                    #pragma unroll
                    for (int d = 0; d < DC; ++d)
                        dot = fmaf(h[n * DC + d], out[d], dot);
                    b[n] += dot;
                }
            }
        }

        float4* o = reinterpret_cast<float4*>(dout + (size_t)(rowBase + tid) * DC);
        o[0] = make_float4(out[0],  out[1],  out[2],  out[3]);
        o[1] = make_float4(out[4],  out[5],  out[6],  out[7]);
        o[2] = make_float4(out[8],  out[9],  out[10], out[11]);
        o[3] = make_float4(out[12], out[13], out[14], out[15]);
    }
}

extern "C" void kernel_launch(void* const* d_in, const int* in_sizes, int n_in,
                              void* d_out, int out_size)
{
    const float* inp = (const float*)d_in[0];
    const float* wk  = (const float*)d_in[1];
    float* out       = (float*)d_out;

    const int rows = in_sizes[0] / K_DIM;   // 16384

    wt_split_kernel<<<(N_DIM * K_DIM + 255) / 256, 256>>>(wk);

    cudaFuncSetAttribute(caps_hmma_kernel,
                         cudaFuncAttributeMaxDynamicSharedMemorySize, SMEM_TOTAL);
    caps_hmma_kernel<<<rows / BM, NTHREAD, SMEM_TOTAL>>>(inp, out, rows);
}

// round 8
// speedup vs baseline: 1.5578x; 1.4399x over previous
#include <cuda_runtime.h>
#include <cuda_fp16.h>
#include <math.h>
#include <stdint.h>

#define K_DIM   2048
#define N_DIM   160
#define NC      10
#define DC      16
#define BM      64
#define BK      64
#define NCHUNK  (K_DIM / BK)          // 32
#define NTHREAD 256
#define HAT_STRIDE 165

// rows padded to 144B: r*144 mod 128 = 16r -> conflict-free ldmatrix
#define ROWB    144
// smem layout (bytes)
#define A_HI    0
#define A_LO    (64 * ROWB)               // 9216
#define B_BASE  (2 * 64 * ROWB)           // 18432
#define B_STAGE (160 * ROWB)              // 23040
#define SMEM_TOTAL (B_BASE + 2 * B_STAGE) // 64512

// Precomputed transposed fp16 weights: Wt[n][k] = fp16(W[k][n])
__device__ __half g_Wt_h[N_DIM * K_DIM];

// ---------------- helpers ----------------
__device__ __forceinline__ uint32_t smem_u32(const void* p) {
    uint32_t a;
    asm("{ .reg .u64 t; cvta.to.shared.u64 t, %1; cvt.u32.u64 %0, t; }" : "=r"(a) : "l"(p));
    return a;
}
__device__ __forceinline__ void ldsm4(uint32_t* d, uint32_t addr) {
    asm volatile("ldmatrix.sync.aligned.m8n8.x4.shared.b16 {%0,%1,%2,%3}, [%4];"
                 : "=r"(d[0]), "=r"(d[1]), "=r"(d[2]), "=r"(d[3]) : "r"(addr));
}
__device__ __forceinline__ void mma16816(float* c, const uint32_t* a,
                                         uint32_t b0, uint32_t b1) {
    asm volatile("mma.sync.aligned.m16n8k16.row.col.f32.f16.f16.f32 "
                 "{%0,%1,%2,%3}, {%4,%5,%6,%7}, {%8,%9}, {%0,%1,%2,%3};"
                 : "+f"(c[0]), "+f"(c[1]), "+f"(c[2]), "+f"(c[3])
                 : "r"(a[0]), "r"(a[1]), "r"(a[2]), "r"(a[3]), "r"(b0), "r"(b1));
}
__device__ __forceinline__ void cp_async16(uint32_t smem_dst, const void* gsrc) {
    asm volatile("cp.async.cg.shared.global [%0], [%1], 16;"
                 :: "r"(smem_dst), "l"(__cvta_generic_to_global(gsrc)) : "memory");
}
#define CP_COMMIT() asm volatile("cp.async.commit_group;" ::: "memory")
#define CP_WAIT0()  asm volatile("cp.async.wait_group 0;" ::: "memory")

__device__ __forceinline__ uint32_t pack_h2(__half x, __half y) {
    __half2 t(x, y);
    return *reinterpret_cast<uint32_t*>(&t);
}

// ---------------- pre-kernel: transpose + fp16 W ----------------
__global__ void wt_prep_kernel(const float* __restrict__ wk) {
    int idx = blockIdx.x * 256 + threadIdx.x;
    if (idx < N_DIM * K_DIM) {
        int n = idx / K_DIM;
        int k = idx % K_DIM;
        g_Wt_h[idx] = __float2half(wk[(size_t)k * N_DIM + n]);
    }
}

// 8 MMAs term-major over a pair of B groups: same-acc RAW distance = 4
#define MMA_PAIR(AH, AL, B0, B1, G0, G1)                       \
    do {                                                       \
        mma16816(acc[2*(G0)+0], AH, B0[0], B0[1]);             \
        mma16816(acc[2*(G0)+1], AH, B0[2], B0[3]);             \
        mma16816(acc[2*(G1)+0], AH, B1[0], B1[1]);             \
        mma16816(acc[2*(G1)+1], AH, B1[2], B1[3]);             \
        mma16816(acc[2*(G0)+0], AL, B0[0], B0[1]);             \
        mma16816(acc[2*(G0)+1], AL, B0[2], B0[3]);             \
        mma16816(acc[2*(G1)+0], AL, B1[0], B1[1]);             \
        mma16816(acc[2*(G1)+1], AL, B1[2], B1[3]);             \
    } while (0)

// ---------------- main fused kernel ----------------
__global__ void __launch_bounds__(NTHREAD, 2)
caps_hmma_kernel(const float* __restrict__ inp, float* __restrict__ dout, int rows)
{
    extern __shared__ char smem[];
    const uint32_t sb = smem_u32(smem);
    const int tid  = threadIdx.x;
    const int lane = tid & 31;
    const int w    = tid >> 5;
    const int rowBase = blockIdx.x * BM;

    // 8 warps: 4 M-groups x 2 N-groups, warp tile 16x80
    const int m0 = (w >> 1) * 16;
    const int n0 = (w & 1) * 80;

    // ldmatrix per-lane offsets (bytes), row stride 144B
    const int rA = (lane & 7) + ((lane >> 3) & 1) * 8;
    const int cA = (lane >> 4) * 16;
    const int aoff = (m0 + rA) * ROWB + cA;

    const int rB = (lane & 7) + ((lane >> 4) ? 8 : 0);
    const int cB = ((lane >> 3) & 1) * 16;
    const int boff = (n0 + rB) * ROWB + cB;

    float acc[10][4];
    #pragma unroll
    for (int j = 0; j < 10; ++j)
        #pragma unroll
        for (int e = 0; e < 4; ++e) acc[j][e] = 0.0f;

    // A global-load mapping: 64 rows x 64 fp32 = 1024 float4; 4/thread
    const int arow = tid >> 2;            // 0..63
    const int aseg0 = tid & 3;            // segs aseg0 + 4j

    // ---- prologue: A(0) + B(0) ----
    {
        #pragma unroll
        for (int j = 0; j < 4; ++j) {
            const int seg = aseg0 + 4 * j;
            float4 v = *reinterpret_cast<const float4*>(
                inp + (size_t)(rowBase + arow) * K_DIM + seg * 4);
            __half hx = __float2half(v.x), hy = __float2half(v.y);
            __half hz = __float2half(v.z), hw = __float2half(v.w);
            uint2 hp = make_uint2(pack_h2(hx, hy), pack_h2(hz, hw));
            uint2 lp = make_uint2(
                pack_h2(__float2half(v.x - __half2float(hx)),
                        __float2half(v.y - __half2float(hy))),
                pack_h2(__float2half(v.z - __half2float(hz)),
                        __float2half(v.w - __half2float(hw))));
            *reinterpret_cast<uint2*>(smem + A_HI + arow * ROWB + seg * 8) = hp;
            *reinterpret_cast<uint2*>(smem + A_LO + arow * ROWB + seg * 8) = lp;
        }
        // B(0): 160 rows x 64 fp16 = 1280 16B segs, 5 per thread
        #pragma unroll
        for (int i = 0; i < 5; ++i) {
            const int u = tid + 256 * i;
            const int n = u >> 3, seg = u & 7;
            cp_async16(sb + B_BASE + n * ROWB + seg * 16,
                       g_Wt_h + (size_t)n * K_DIM + seg * 8);
        }
        CP_COMMIT();
        CP_WAIT0();
    }
    __syncthreads();

    // ---- main loop: A single-stage (reg prefetch), B double-buffered ----
    for (int c = 0; c < NCHUNK; ++c) {
        const uint32_t bcur = sb + B_BASE + (c & 1) * B_STAGE;
        const int has_next = (c + 1) < NCHUNK;

        float4 ra[4];
        if (has_next) {
            const int kbase = (c + 1) * BK;
            const uint32_t bnxt = sb + B_BASE + ((c + 1) & 1) * B_STAGE;
            #pragma unroll
            for (int i = 0; i < 5; ++i) {
                const int u = tid + 256 * i;
                const int n = u >> 3, seg = u & 7;
                cp_async16(bnxt + n * ROWB + seg * 16,
                           g_Wt_h + (size_t)n * K_DIM + kbase + seg * 8);
            }
            CP_COMMIT();
            #pragma unroll
            for (int j = 0; j < 4; ++j)
                ra[j] = *reinterpret_cast<const float4*>(
                    inp + (size_t)(rowBase + arow) * K_DIM + kbase + (aseg0 + 4 * j) * 4);
        }

        // ---- compute chunk c: 4 K-steps, 20 MMAs each ----
        const uint32_t ah_base = sb + A_HI + aoff;
        const uint32_t al_base = sb + A_LO + aoff;
        const uint32_t bh_base = bcur + boff;
        #pragma unroll
        for (int ks = 0; ks < 4; ++ks) {
            uint32_t ah[4], al[4];
            ldsm4(ah, ah_base + ks * 32);
            ldsm4(al, al_base + ks * 32);
            {
                uint32_t b0[4], b1[4];
                ldsm4(b0, bh_base + 0 * 16 * ROWB + ks * 32);
                ldsm4(b1, bh_base + 1 * 16 * ROWB + ks * 32);
                MMA_PAIR(ah, al, b0, b1, 0, 1);
            }
            {
                uint32_t b0[4], b1[4];
                ldsm4(b0, bh_base + 2 * 16 * ROWB + ks * 32);
                ldsm4(b1, bh_base + 3 * 16 * ROWB + ks * 32);
                MMA_PAIR(ah, al, b0, b1, 2, 3);
            }
            {
                uint32_t b0[4];
                ldsm4(b0, bh_base + 4 * 16 * ROWB + ks * 32);
                mma16816(acc[8], ah, b0[0], b0[1]);
                mma16816(acc[9], ah, b0[2], b0[3]);
                mma16816(acc[8], al, b0[0], b0[1]);
                mma16816(acc[9], al, b0[2], b0[3]);
            }
        }

        __syncthreads();   // everyone done reading A stage

        if (has_next) {
            #pragma unroll
            for (int j = 0; j < 4; ++j) {
                const int seg = aseg0 + 4 * j;
                float4 v = ra[j];
                __half hx = __float2half(v.x), hy = __float2half(v.y);
                __half hz = __float2half(v.z), hw = __float2half(v.w);
                uint2 hp = make_uint2(pack_h2(hx, hy), pack_h2(hz, hw));
                uint2 lp = make_uint2(
                    pack_h2(__float2half(v.x - __half2float(hx)),
                            __float2half(v.y - __half2float(hy))),
                    pack_h2(__float2half(v.z - __half2float(hz)),
                            __float2half(v.w - __half2float(hw))));
                *reinterpret_cast<uint2*>(smem + A_HI + arow * ROWB + seg * 8) = hp;
                *reinterpret_cast<uint2*>(smem + A_LO + arow * ROWB + seg * 8) = lp;
            }
            CP_WAIT0();        // B(c+1) landed
            __syncthreads();
        }
    }
    __syncthreads();

    // ---- write C frags to padded smem hat tile ----
    float* hat = reinterpret_cast<float*>(smem);
    {
        const int r0 = m0 + (lane >> 2);
        const int cbase = n0 + (lane & 3) * 2;
        #pragma unroll
        for (int j = 0; j < 10; ++j) {
            const int col = cbase + 8 * j;
            hat[r0 * HAT_STRIDE + col]           = acc[j][0];
            hat[r0 * HAT_STRIDE + col + 1]       = acc[j][1];
            hat[(r0 + 8) * HAT_STRIDE + col]     = acc[j][2];
            hat[(r0 + 8) * HAT_STRIDE + col + 1] = acc[j][3];
        }
    }
    __syncthreads();

    // ---- dynamic routing: one thread per row ----
    if (tid < BM) {
        const float* h = &hat[tid * HAT_STRIDE];

        float b[NC];
        #pragma unroll
        for (int n = 0; n < NC; ++n) b[n] = 0.0f;
        float out[DC];

        #pragma unroll
        for (int it = 0; it < 3; ++it) {
            float m = b[0];
            #pragma unroll
            for (int n = 1; n < NC; ++n) m = fmaxf(m, b[n]);
            float cc[NC];
            float se = 0.0f;
            #pragma unroll
            for (int n = 0; n < NC; ++n) { cc[n] = expf(b[n] - m); se += cc[n]; }
            const float inv = 1.0f / se;

            float s[DC];
            #pragma unroll
            for (int d = 0; d < DC; ++d) s[d] = 0.0f;
            #pragma unroll
            for (int n = 0; n < NC; ++n) {
                const float cn = cc[n] * inv;
                #pragma unroll
                for (int d = 0; d < DC; ++d)
                    s[d] = fmaf(cn, h[n * DC + d], s[d]);
            }

            float s2 = 0.0f;
            #pragma unroll
            for (int d = 0; d < DC; ++d) s2 = fmaf(s[d], s[d], s2);
            const float scale = s2 / ((1.0f + s2) * sqrtf(s2 + 1e-7f));
            #pragma unroll
            for (int d = 0; d < DC; ++d) out[d] = scale * s[d];

            if (it < 2) {
                #pragma unroll
                for (int n = 0; n < NC; ++n) {
                    float dot = 0.0f;
                    #pragma unroll
                    for (int d = 0; d < DC; ++d)
                        dot = fmaf(h[n * DC + d], out[d], dot);
                    b[n] += dot;
                }
            }
        }

        float4* o = reinterpret_cast<float4*>(dout + (size_t)(rowBase + tid) * DC);
        o[0] = make_float4(out[0],  out[1],  out[2],  out[3]);
        o[1] = make_float4(out[4],  out[5],  out[6],  out[7]);
        o[2] = make_float4(out[8],  out[9],  out[10], out[11]);
        o[3] = make_float4(out[12], out[13], out[14], out[15]);
    }
}

extern "C" void kernel_launch(void* const* d_in, const int* in_sizes, int n_in,
                              void* d_out, int out_size)
{
    const float* inp = (const float*)d_in[0];
    const float* wk  = (const float*)d_in[1];
    float* out       = (float*)d_out;

    const int rows = in_sizes[0] / K_DIM;   // 16384

    wt_prep_kernel<<<(N_DIM * K_DIM + 255) / 256, 256>>>(wk);

    cudaFuncSetAttribute(caps_hmma_kernel,
                         cudaFuncAttributeMaxDynamicSharedMemorySize, SMEM_TOTAL);
    caps_hmma_kernel<<<rows / BM, NTHREAD, SMEM_TOTAL>>>(inp, out, rows);
}

// round 9
// speedup vs baseline: 1.8636x; 1.1963x over previous
#include <cuda_runtime.h>
#include <cuda_fp16.h>
#include <math.h>
#include <stdint.h>

#define K_DIM   2048
#define N_DIM   160
#define NC      10
#define DC      16
#define BM      64
#define BK      64
#define NCHUNK  (K_DIM / BK)          // 32
#define NTHREAD 256
#define HAT_STRIDE 165

// rows padded to 144B: r*144 mod 128 = 16r -> conflict-free ldmatrix
#define ROWB    144
// smem layout (bytes)
#define A_HI    0
#define B_BASE  (64 * ROWB)               // 9216
#define B_STAGE (160 * ROWB)              // 23040
#define SMEM_TOTAL (B_BASE + 2 * B_STAGE) // 55296

// Precomputed transposed fp16 weights: Wt[n][k] = fp16(W[k][n])
__device__ __half g_Wt_h[N_DIM * K_DIM];

// ---------------- helpers ----------------
__device__ __forceinline__ uint32_t smem_u32(const void* p) {
    uint32_t a;
    asm("{ .reg .u64 t; cvta.to.shared.u64 t, %1; cvt.u32.u64 %0, t; }" : "=r"(a) : "l"(p));
    return a;
}
__device__ __forceinline__ void ldsm4(uint32_t* d, uint32_t addr) {
    asm volatile("ldmatrix.sync.aligned.m8n8.x4.shared.b16 {%0,%1,%2,%3}, [%4];"
                 : "=r"(d[0]), "=r"(d[1]), "=r"(d[2]), "=r"(d[3]) : "r"(addr));
}
__device__ __forceinline__ void mma16816(float* c, const uint32_t* a,
                                         uint32_t b0, uint32_t b1) {
    asm volatile("mma.sync.aligned.m16n8k16.row.col.f32.f16.f16.f32 "
                 "{%0,%1,%2,%3}, {%4,%5,%6,%7}, {%8,%9}, {%0,%1,%2,%3};"
                 : "+f"(c[0]), "+f"(c[1]), "+f"(c[2]), "+f"(c[3])
                 : "r"(a[0]), "r"(a[1]), "r"(a[2]), "r"(a[3]), "r"(b0), "r"(b1));
}
__device__ __forceinline__ void cp_async16(uint32_t smem_dst, const void* gsrc) {
    asm volatile("cp.async.cg.shared.global [%0], [%1], 16;"
                 :: "r"(smem_dst), "l"(__cvta_generic_to_global(gsrc)) : "memory");
}
#define CP_COMMIT() asm volatile("cp.async.commit_group;" ::: "memory")
#define CP_WAIT0()  asm volatile("cp.async.wait_group 0;" ::: "memory")

__device__ __forceinline__ uint32_t pack_h2(__half x, __half y) {
    __half2 t(x, y);
    return *reinterpret_cast<uint32_t*>(&t);
}

// ---------------- pre-kernel: transpose + fp16 W ----------------
__global__ void wt_prep_kernel(const float* __restrict__ wk) {
    int idx = blockIdx.x * 256 + threadIdx.x;
    if (idx < N_DIM * K_DIM) {
        int n = idx / K_DIM;
        int k = idx % K_DIM;
        g_Wt_h[idx] = __float2half(wk[(size_t)k * N_DIM + n]);
    }
}

// ---------------- main fused kernel ----------------
__global__ void __launch_bounds__(NTHREAD, 2)
caps_hmma_kernel(const float* __restrict__ inp, float* __restrict__ dout, int rows)
{
    extern __shared__ char smem[];
    const uint32_t sb = smem_u32(smem);
    const int tid  = threadIdx.x;
    const int lane = tid & 31;
    const int w    = tid >> 5;
    const int rowBase = blockIdx.x * BM;

    // 8 warps: 4 M-groups x 2 N-groups, warp tile 16x80
    const int m0 = (w >> 1) * 16;
    const int n0 = (w & 1) * 80;

    // ldmatrix per-lane offsets (bytes), row stride 144B
    const int rA = (lane & 7) + ((lane >> 3) & 1) * 8;
    const int cA = (lane >> 4) * 16;
    const int aoff = (m0 + rA) * ROWB + cA;

    const int rB = (lane & 7) + ((lane >> 4) ? 8 : 0);
    const int cB = ((lane >> 3) & 1) * 16;
    const int boff = (n0 + rB) * ROWB + cB;

    float acc[10][4];
    #pragma unroll
    for (int j = 0; j < 10; ++j)
        #pragma unroll
        for (int e = 0; e < 4; ++e) acc[j][e] = 0.0f;

    // A global-load mapping: 64 rows x 64 fp32 = 1024 float4; 4/thread
    const int arow = tid >> 2;            // 0..63
    const int aseg0 = tid & 3;            // segs aseg0 + 4j

    // ---- prologue: A(0) + B(0) ----
    {
        #pragma unroll
        for (int j = 0; j < 4; ++j) {
            const int seg = aseg0 + 4 * j;
            float4 v = *reinterpret_cast<const float4*>(
                inp + (size_t)(rowBase + arow) * K_DIM + seg * 4);
            uint2 hp = make_uint2(pack_h2(__float2half(v.x), __float2half(v.y)),
                                  pack_h2(__float2half(v.z), __float2half(v.w)));
            *reinterpret_cast<uint2*>(smem + A_HI + arow * ROWB + seg * 8) = hp;
        }
        // B(0): 160 rows x 64 fp16 = 1280 16B segs, 5 per thread
        #pragma unroll
        for (int i = 0; i < 5; ++i) {
            const int u = tid + 256 * i;
            const int n = u >> 3, seg = u & 7;
            cp_async16(sb + B_BASE + n * ROWB + seg * 16,
                       g_Wt_h + (size_t)n * K_DIM + seg * 8);
        }
        CP_COMMIT();
        CP_WAIT0();
    }
    __syncthreads();

    // ---- main loop: A single-stage (reg prefetch), B double-buffered ----
    for (int c = 0; c < NCHUNK; ++c) {
        const uint32_t bcur = sb + B_BASE + (c & 1) * B_STAGE;
        const int has_next = (c + 1) < NCHUNK;

        float4 ra[4];
        if (has_next) {
            const int kbase = (c + 1) * BK;
            const uint32_t bnxt = sb + B_BASE + ((c + 1) & 1) * B_STAGE;
            #pragma unroll
            for (int i = 0; i < 5; ++i) {
                const int u = tid + 256 * i;
                const int n = u >> 3, seg = u & 7;
                cp_async16(bnxt + n * ROWB + seg * 16,
                           g_Wt_h + (size_t)n * K_DIM + kbase + seg * 8);
            }
            CP_COMMIT();
            #pragma unroll
            for (int j = 0; j < 4; ++j)
                ra[j] = *reinterpret_cast<const float4*>(
                    inp + (size_t)(rowBase + arow) * K_DIM + kbase + (aseg0 + 4 * j) * 4);
        }

        // ---- compute chunk c: 4 K-steps, 10 MMAs each (acc RAW distance 10) ----
        const uint32_t ah_base = sb + A_HI + aoff;
        const uint32_t bh_base = bcur + boff;
        #pragma unroll
        for (int ks = 0; ks < 4; ++ks) {
            uint32_t ah[4];
            ldsm4(ah, ah_base + ks * 32);
            uint32_t b0[4], b1[4], b2[4], b3[4], b4[4];
            ldsm4(b0, bh_base + 0 * 16 * ROWB + ks * 32);
            ldsm4(b1, bh_base + 1 * 16 * ROWB + ks * 32);
            ldsm4(b2, bh_base + 2 * 16 * ROWB + ks * 32);
            ldsm4(b3, bh_base + 3 * 16 * ROWB + ks * 32);
            ldsm4(b4, bh_base + 4 * 16 * ROWB + ks * 32);
            mma16816(acc[0], ah, b0[0], b0[1]);
            mma16816(acc[1], ah, b0[2], b0[3]);
            mma16816(acc[2], ah, b1[0], b1[1]);
            mma16816(acc[3], ah, b1[2], b1[3]);
            mma16816(acc[4], ah, b2[0], b2[1]);
            mma16816(acc[5], ah, b2[2], b2[3]);
            mma16816(acc[6], ah, b3[0], b3[1]);
            mma16816(acc[7], ah, b3[2], b3[3]);
            mma16816(acc[8], ah, b4[0], b4[1]);
            mma16816(acc[9], ah, b4[2], b4[3]);
        }

        __syncthreads();   // everyone done reading A stage

        if (has_next) {
            #pragma unroll
            for (int j = 0; j < 4; ++j) {
                const int seg = aseg0 + 4 * j;
                float4 v = ra[j];
                uint2 hp = make_uint2(pack_h2(__float2half(v.x), __float2half(v.y)),
                                      pack_h2(__float2half(v.z), __float2half(v.w)));
                *reinterpret_cast<uint2*>(smem + A_HI + arow * ROWB + seg * 8) = hp;
            }
            CP_WAIT0();        // B(c+1) landed
            __syncthreads();
        }
    }
    __syncthreads();

    // ---- write C frags to padded smem hat tile ----
    float* hat = reinterpret_cast<float*>(smem);
    {
        const int r0 = m0 + (lane >> 2);
        const int cbase = n0 + (lane & 3) * 2;
        #pragma unroll
        for (int j = 0; j < 10; ++j) {
            const int col = cbase + 8 * j;
            hat[r0 * HAT_STRIDE + col]           = acc[j][0];
            hat[r0 * HAT_STRIDE + col + 1]       = acc[j][1];
            hat[(r0 + 8) * HAT_STRIDE + col]     = acc[j][2];
            hat[(r0 + 8) * HAT_STRIDE + col + 1] = acc[j][3];
        }
    }
    __syncthreads();

    // ---- dynamic routing: one thread per row ----
    if (tid < BM) {
        const float* h = &hat[tid * HAT_STRIDE];

        float b[NC];
        #pragma unroll
        for (int n = 0; n < NC; ++n) b[n] = 0.0f;
        float out[DC];

        #pragma unroll
        for (int it = 0; it < 3; ++it) {
            float m = b[0];
            #pragma unroll
            for (int n = 1; n < NC; ++n) m = fmaxf(m, b[n]);
            float cc[NC];
            float se = 0.0f;
            #pragma unroll
            for (int n = 0; n < NC; ++n) { cc[n] = expf(b[n] - m); se += cc[n]; }
            const float inv = 1.0f / se;

            float s[DC];
            #pragma unroll
            for (int d = 0; d < DC; ++d) s[d] = 0.0f;
            #pragma unroll
            for (int n = 0; n < NC; ++n) {
                const float cn = cc[n] * inv;
                #pragma unroll
                for (int d = 0; d < DC; ++d)
                    s[d] = fmaf(cn, h[n * DC + d], s[d]);
            }

            float s2 = 0.0f;
            #pragma unroll
            for (int d = 0; d < DC; ++d) s2 = fmaf(s[d], s[d], s2);
            const float scale = s2 / ((1.0f + s2) * sqrtf(s2 + 1e-7f));
            #pragma unroll
            for (int d = 0; d < DC; ++d) out[d] = scale * s[d];

            if (it < 2) {
                #pragma unroll
                for (int n = 0; n < NC; ++n) {
                    float dot = 0.0f;
                    #pragma unroll
                    for (int d = 0; d < DC; ++d)
                        dot = fmaf(h[n * DC + d], out[d], dot);
                    b[n] += dot;
                }
            }
        }

        float4* o = reinterpret_cast<float4*>(dout + (size_t)(rowBase + tid) * DC);
        o[0] = make_float4(out[0],  out[1],  out[2],  out[3]);
        o[1] = make_float4(out[4],  out[5],  out[6],  out[7]);
        o[2] = make_float4(out[8],  out[9],  out[10], out[11]);
        o[3] = make_float4(out[12], out[13], out[14], out[15]);
    }
}

extern "C" void kernel_launch(void* const* d_in, const int* in_sizes, int n_in,
                              void* d_out, int out_size)
{
    const float* inp = (const float*)d_in[0];
    const float* wk  = (const float*)d_in[1];
    float* out       = (float*)d_out;

    const int rows = in_sizes[0] / K_DIM;   // 16384

    wt_prep_kernel<<<(N_DIM * K_DIM + 255) / 256, 256>>>(wk);

    cudaFuncSetAttribute(caps_hmma_kernel,
                         cudaFuncAttributeMaxDynamicSharedMemorySize, SMEM_TOTAL);
    caps_hmma_kernel<<<rows / BM, NTHREAD, SMEM_TOTAL>>>(inp, out, rows);
}

// round 10
// speedup vs baseline: 1.9918x; 1.0688x over previous
#include <cuda_runtime.h>
#include <cuda_fp16.h>
#include <math.h>
#include <stdint.h>

#define K_DIM   2048
#define N_DIM   160
#define NC      10
#define DC      16
#define BM      64
#define BK      64
#define NCHUNK  (K_DIM / BK)          // 32
#define NTHREAD 256
#define HAT_STRIDE 165

// A: raw fp32, row stride 288B (72 words; 72 mod 32 = 8 -> conflict-free LDS.64)
#define ROWA    288
#define A_BASE  0
#define A_STAGE (64 * ROWA)               // 18432
// B: fp16 transposed, row stride 144B (conflict-free ldmatrix)
#define ROWB    144
#define B_BASE  (2 * A_STAGE)             // 36864
#define B_STAGE (160 * ROWB)              // 23040
#define SMEM_TOTAL (B_BASE + 2 * B_STAGE) // 82944

// Precomputed transposed fp16 weights: Wt[n][k] = fp16(W[k][n])
__device__ __half g_Wt_h[N_DIM * K_DIM];

// ---------------- helpers ----------------
__device__ __forceinline__ uint32_t smem_u32(const void* p) {
    uint32_t a;
    asm("{ .reg .u64 t; cvta.to.shared.u64 t, %1; cvt.u32.u64 %0, t; }" : "=r"(a) : "l"(p));
    return a;
}
__device__ __forceinline__ void ldsm4(uint32_t* d, uint32_t addr) {
    asm volatile("ldmatrix.sync.aligned.m8n8.x4.shared.b16 {%0,%1,%2,%3}, [%4];"
                 : "=r"(d[0]), "=r"(d[1]), "=r"(d[2]), "=r"(d[3]) : "r"(addr));
}
// LDS.64 of two consecutive fp32 -> packed fp16x2 {hi=odd col, lo=even col}
__device__ __forceinline__ uint32_t lds_cvt(uint32_t addr) {
    float fx, fy;
    asm volatile("ld.shared.v2.f32 {%0,%1}, [%2];" : "=f"(fx), "=f"(fy) : "r"(addr));
    uint32_t d;
    asm("cvt.rn.f16x2.f32 %0, %1, %2;" : "=r"(d) : "f"(fy), "f"(fx));
    return d;
}
__device__ __forceinline__ void mma16816(float* c, const uint32_t* a,
                                         uint32_t b0, uint32_t b1) {
    asm volatile("mma.sync.aligned.m16n8k16.row.col.f32.f16.f16.f32 "
                 "{%0,%1,%2,%3}, {%4,%5,%6,%7}, {%8,%9}, {%0,%1,%2,%3};"
                 : "+f"(c[0]), "+f"(c[1]), "+f"(c[2]), "+f"(c[3])
                 : "r"(a[0]), "r"(a[1]), "r"(a[2]), "r"(a[3]), "r"(b0), "r"(b1));
}
__device__ __forceinline__ void cp_async16(uint32_t smem_dst, const void* gsrc) {
    asm volatile("cp.async.cg.shared.global [%0], [%1], 16;"
                 :: "r"(smem_dst), "l"(__cvta_generic_to_global(gsrc)) : "memory");
}
#define CP_COMMIT() asm volatile("cp.async.commit_group;" ::: "memory")
#define CP_WAIT0()  asm volatile("cp.async.wait_group 0;" ::: "memory")

// ---------------- pre-kernel: transpose + fp16 W ----------------
__global__ void wt_prep_kernel(const float* __restrict__ wk) {
    int idx = blockIdx.x * 256 + threadIdx.x;
    if (idx < N_DIM * K_DIM) {
        int n = idx / K_DIM;
        int k = idx % K_DIM;
        g_Wt_h[idx] = __float2half(wk[(size_t)k * N_DIM + n]);
    }
}

// ---------------- main fused kernel ----------------
__global__ void __launch_bounds__(NTHREAD, 2)
caps_hmma_kernel(const float* __restrict__ inp, float* __restrict__ dout, int rows)
{
    extern __shared__ char smem[];
    const uint32_t sb = smem_u32(smem);
    const int tid  = threadIdx.x;
    const int lane = tid & 31;
    const int w    = tid >> 5;
    const int rowBase = blockIdx.x * BM;

    // 8 warps: 4 M-groups x 2 N-groups, warp tile 16x80
    const int m0 = (w >> 1) * 16;
    const int n0 = (w & 1) * 80;

    // A fragment base (LDS.64): row = m0 + lane/4, col pair = 2*(lane%4)
    const int a_lane_off = (m0 + (lane >> 2)) * ROWA + (lane & 3) * 8;

    // B ldmatrix per-lane offset
    const int rB = (lane & 7) + ((lane >> 4) ? 8 : 0);
    const int cB = ((lane >> 3) & 1) * 16;
    const int boff = (n0 + rB) * ROWB + cB;

    float acc[10][4];
    #pragma unroll
    for (int j = 0; j < 10; ++j)
        #pragma unroll
        for (int e = 0; e < 4; ++e) acc[j][e] = 0.0f;

    // ---- cp.async mappings ----
    // A: 64 rows x 64 fp32 = 1024 x 16B segs, 4/thread
    // B: 160 rows x 64 fp16 = 1280 x 16B segs, 5/thread
    #define ISSUE_CHUNK(stage_sel, kbase)                                        \
        do {                                                                     \
            const uint32_t a_dst = sb + A_BASE + (stage_sel) * A_STAGE;          \
            _Pragma("unroll")                                                    \
            for (int i = 0; i < 4; ++i) {                                        \
                const int u = tid + 256 * i;                                     \
                const int r = u >> 4, seg = u & 15;                              \
                cp_async16(a_dst + r * ROWA + seg * 16,                          \
                           inp + (size_t)(rowBase + r) * K_DIM + (kbase) + seg * 4); \
            }                                                                    \
            const uint32_t b_dst = sb + B_BASE + (stage_sel) * B_STAGE;          \
            _Pragma("unroll")                                                    \
            for (int i = 0; i < 5; ++i) {                                        \
                const int u = tid + 256 * i;                                     \
                const int n = u >> 3, seg = u & 7;                               \
                cp_async16(b_dst + n * ROWB + seg * 16,                          \
                           g_Wt_h + (size_t)n * K_DIM + (kbase) + seg * 8);      \
            }                                                                    \
            CP_COMMIT();                                                         \
        } while (0)

    // ---- prologue: stage 0 = chunk 0 ----
    ISSUE_CHUNK(0, 0);
    CP_WAIT0();
    __syncthreads();

    // ---- main loop: single barrier per chunk ----
    for (int c = 0; c < NCHUNK; ++c) {
        const int s = c & 1;
        const int has_next = (c + 1) < NCHUNK;

        if (has_next)
            ISSUE_CHUNK(s ^ 1, (c + 1) * BK);

        // ---- compute chunk c: 4 K-steps, 10 MMAs each ----
        const uint32_t a_base = sb + A_BASE + s * A_STAGE + a_lane_off;
        const uint32_t b_base = sb + B_BASE + s * B_STAGE + boff;
        #pragma unroll
        for (int ks = 0; ks < 4; ++ks) {
            uint32_t ah[4];
            ah[0] = lds_cvt(a_base + ks * 64);            // (row, ks*16 + 2t)
            ah[1] = lds_cvt(a_base + ks * 64 + 8 * ROWA); // row + 8
            ah[2] = lds_cvt(a_base + ks * 64 + 32);       // col + 8
            ah[3] = lds_cvt(a_base + ks * 64 + 8 * ROWA + 32);
            uint32_t b0[4], b1[4], b2[4], b3[4], b4[4];
            ldsm4(b0, b_base + 0 * 16 * ROWB + ks * 32);
            ldsm4(b1, b_base + 1 * 16 * ROWB + ks * 32);
            ldsm4(b2, b_base + 2 * 16 * ROWB + ks * 32);
            ldsm4(b3, b_base + 3 * 16 * ROWB + ks * 32);
            ldsm4(b4, b_base + 4 * 16 * ROWB + ks * 32);
            mma16816(acc[0], ah, b0[0], b0[1]);
            mma16816(acc[1], ah, b0[2], b0[3]);
            mma16816(acc[2], ah, b1[0], b1[1]);
            mma16816(acc[3], ah, b1[2], b1[3]);
            mma16816(acc[4], ah, b2[0], b2[1]);
            mma16816(acc[5], ah, b2[2], b2[3]);
            mma16816(acc[6], ah, b3[0], b3[1]);
            mma16816(acc[7], ah, b3[2], b3[3]);
            mma16816(acc[8], ah, b4[0], b4[1]);
            mma16816(acc[9], ah, b4[2], b4[3]);
        }

        if (has_next)
            CP_WAIT0();          // next stage landed
        __syncthreads();         // single barrier: stage flip
    }

    // ---- write C frags to padded smem hat tile ----
    float* hat = reinterpret_cast<float*>(smem);
    {
        const int r0 = m0 + (lane >> 2);
        const int cbase = n0 + (lane & 3) * 2;
        #pragma unroll
        for (int j = 0; j < 10; ++j) {
            const int col = cbase + 8 * j;
            hat[r0 * HAT_STRIDE + col]           = acc[j][0];
            hat[r0 * HAT_STRIDE + col + 1]       = acc[j][1];
            hat[(r0 + 8) * HAT_STRIDE + col]     = acc[j][2];
            hat[(r0 + 8) * HAT_STRIDE + col + 1] = acc[j][3];
        }
    }
    __syncthreads();

    // ---- dynamic routing: one thread per row ----
    if (tid < BM) {
        const float* h = &hat[tid * HAT_STRIDE];

        float b[NC];
        #pragma unroll
        for (int n = 0; n < NC; ++n) b[n] = 0.0f;
        float out[DC];

        #pragma unroll
        for (int it = 0; it < 3; ++it) {
            float m = b[0];
            #pragma unroll
            for (int n = 1; n < NC; ++n) m = fmaxf(m, b[n]);
            float cc[NC];
            float se = 0.0f;
            #pragma unroll
            for (int n = 0; n < NC; ++n) { cc[n] = expf(b[n] - m); se += cc[n]; }
            const float inv = 1.0f / se;

            float s[DC];
            #pragma unroll
            for (int d = 0; d < DC; ++d) s[d] = 0.0f;
            #pragma unroll
            for (int n = 0; n < NC; ++n) {
                const float cn = cc[n] * inv;
                #pragma unroll
                for (int d = 0; d < DC; ++d)
                    s[d] = fmaf(cn, h[n * DC + d], s[d]);
            }

            float s2 = 0.0f;
            #pragma unroll
            for (int d = 0; d < DC; ++d) s2 = fmaf(s[d], s[d], s2);
            const float scale = s2 / ((1.0f + s2) * sqrtf(s2 + 1e-7f));
            #pragma unroll
            for (int d = 0; d < DC; ++d) out[d] = scale * s[d];

            if (it < 2) {
                #pragma unroll
                for (int n = 0; n < NC; ++n) {
                    float dot = 0.0f;
                    #pragma unroll
                    for (int d = 0; d < DC; ++d)
                        dot = fmaf(h[n * DC + d], out[d], dot);
                    b[n] += dot;
                }
            }
        }

        float4* o = reinterpret_cast<float4*>(dout + (size_t)(rowBase + tid) * DC);
        o[0] = make_float4(out[0],  out[1],  out[2],  out[3]);
        o[1] = make_float4(out[4],  out[5],  out[6],  out[7]);
        o[2] = make_float4(out[8],  out[9],  out[10], out[11]);
        o[3] = make_float4(out[12], out[13], out[14], out[15]);
    }
}

extern "C" void kernel_launch(void* const* d_in, const int* in_sizes, int n_in,
                              void* d_out, int out_size)
{
    const float* inp = (const float*)d_in[0];
    const float* wk  = (const float*)d_in[1];
    float* out       = (float*)d_out;

    const int rows = in_sizes[0] / K_DIM;   // 16384

    wt_prep_kernel<<<(N_DIM * K_DIM + 255) / 256, 256>>>(wk);

    cudaFuncSetAttribute(caps_hmma_kernel,
                         cudaFuncAttributeMaxDynamicSharedMemorySize, SMEM_TOTAL);
    caps_hmma_kernel<<<rows / BM, NTHREAD, SMEM_TOTAL>>>(inp, out, rows);
}

// round 11
// speedup vs baseline: 1.9927x; 1.0005x over previous
#include <cuda_runtime.h>
#include <cuda_fp16.h>
#include <math.h>
#include <stdint.h>

#define K_DIM   2048
#define N_DIM   160
#define NC      10
#define DC      16
#define BM      64
#define BK      64
#define NCHUNK  (K_DIM / BK)          // 32
#define NTHREAD 128
#define HAT_STRIDE 165

// B: fp16 transposed, row stride 144B (conflict-free ldmatrix), double-buffered
#define ROWB    144
#define B_STAGE (160 * ROWB)              // 23040
#define SMEM_TOTAL (2 * B_STAGE)          // 46080 >= hat tile 42240

// Precomputed transposed fp16 weights: Wt[n][k] = fp16(W[k][n])
__device__ __half g_Wt_h[N_DIM * K_DIM];

// ---------------- helpers ----------------
__device__ __forceinline__ uint32_t smem_u32(const void* p) {
    uint32_t a;
    asm("{ .reg .u64 t; cvta.to.shared.u64 t, %1; cvt.u32.u64 %0, t; }" : "=r"(a) : "l"(p));
    return a;
}
__device__ __forceinline__ void ldsm4(uint32_t* d, uint32_t addr) {
    asm volatile("ldmatrix.sync.aligned.m8n8.x4.shared.b16 {%0,%1,%2,%3}, [%4];"
                 : "=r"(d[0]), "=r"(d[1]), "=r"(d[2]), "=r"(d[3]) : "r"(addr));
}
__device__ __forceinline__ void mma16816(float* c, const uint32_t* a,
                                         uint32_t b0, uint32_t b1) {
    asm volatile("mma.sync.aligned.m16n8k16.row.col.f32.f16.f16.f32 "
                 "{%0,%1,%2,%3}, {%4,%5,%6,%7}, {%8,%9}, {%0,%1,%2,%3};"
                 : "+f"(c[0]), "+f"(c[1]), "+f"(c[2]), "+f"(c[3])
                 : "r"(a[0]), "r"(a[1]), "r"(a[2]), "r"(a[3]), "r"(b0), "r"(b1));
}
__device__ __forceinline__ void cp_async16(uint32_t smem_dst, const void* gsrc) {
    asm volatile("cp.async.cg.shared.global [%0], [%1], 16;"
                 :: "r"(smem_dst), "l"(__cvta_generic_to_global(gsrc)) : "memory");
}
#define CP_COMMIT() asm volatile("cp.async.commit_group;" ::: "memory")
#define CP_WAIT0()  asm volatile("cp.async.wait_group 0;" ::: "memory")

// pack two fp32 (lo, hi) -> fp16x2 reg (lo in low half)
__device__ __forceinline__ uint32_t cvt_h2(float lo, float hi) {
    uint32_t d;
    asm("cvt.rn.f16x2.f32 %0, %1, %2;" : "=r"(d) : "f"(hi), "f"(lo));
    return d;
}

// ---------------- pre-kernel: transpose + fp16 W ----------------
__global__ void wt_prep_kernel(const float* __restrict__ wk) {
    int idx = blockIdx.x * 256 + threadIdx.x;
    if (idx < N_DIM * K_DIM) {
        int n = idx / K_DIM;
        int k = idx % K_DIM;
        g_Wt_h[idx] = __float2half(wk[(size_t)k * N_DIM + n]);
    }
}

// ---------------- main fused kernel ----------------
__global__ void __launch_bounds__(NTHREAD, 2)
caps_hmma_kernel(const float* __restrict__ inp, float* __restrict__ dout, int rows)
{
    extern __shared__ char smem[];
    const uint32_t sb = smem_u32(smem);
    const int tid  = threadIdx.x;
    const int lane = tid & 31;
    const int w    = tid >> 5;
    const int rowBase = blockIdx.x * BM;

    // 4 warps: 4 M-groups x 1 N-group, warp tile 16x160
    const int m0 = w * 16;

    // A direct-LDG per-lane row pointers (fragment layout of m16n8k16)
    const float* arow0 = inp + (size_t)(rowBase + m0 + (lane >> 2)) * K_DIM + (lane & 3) * 2;
    const float* arow1 = arow0 + 8 * K_DIM;

    // B ldmatrix per-lane offset
    const int rB = (lane & 7) + ((lane >> 4) ? 8 : 0);
    const int cB = ((lane >> 3) & 1) * 16;
    const int boff = rB * ROWB + cB;

    float acc[20][4];
    #pragma unroll
    for (int j = 0; j < 20; ++j)
        #pragma unroll
        for (int e = 0; e < 4; ++e) acc[j][e] = 0.0f;

    // A fragments: current chunk (fp16x2) and next chunk (raw fp32 pairs)
    uint32_t acur[4][4];
    float2 ranext[4][4];

    #define LOAD_A(kbase)                                                     \
        do {                                                                  \
            _Pragma("unroll")                                                 \
            for (int ks = 0; ks < 4; ++ks) {                                  \
                const int off = (kbase) + ks * 16;                            \
                ranext[ks][0] = *reinterpret_cast<const float2*>(arow0 + off);     \
                ranext[ks][1] = *reinterpret_cast<const float2*>(arow1 + off);     \
                ranext[ks][2] = *reinterpret_cast<const float2*>(arow0 + off + 8); \
                ranext[ks][3] = *reinterpret_cast<const float2*>(arow1 + off + 8); \
            }                                                                 \
        } while (0)

    #define CVT_A()                                                           \
        do {                                                                  \
            _Pragma("unroll")                                                 \
            for (int ks = 0; ks < 4; ++ks)                                    \
                _Pragma("unroll")                                             \
                for (int e = 0; e < 4; ++e)                                   \
                    acur[ks][e] = cvt_h2(ranext[ks][e].x, ranext[ks][e].y);   \
        } while (0)

    // B cp.async: 160 rows x 64 fp16 = 1280 16B segs, 10/thread
    #define ISSUE_B(stage_sel, kbase)                                         \
        do {                                                                  \
            const uint32_t b_dst = sb + (stage_sel) * B_STAGE;                \
            _Pragma("unroll")                                                 \
            for (int i = 0; i < 10; ++i) {                                    \
                const int u = tid + 128 * i;                                  \
                const int n = u >> 3, seg = u & 7;                            \
                cp_async16(b_dst + n * ROWB + seg * 16,                       \
                           g_Wt_h + (size_t)n * K_DIM + (kbase) + seg * 8);   \
            }                                                                 \
            CP_COMMIT();                                                      \
        } while (0)

    // ---- prologue ----
    ISSUE_B(0, 0);
    LOAD_A(0);
    CVT_A();
    CP_WAIT0();
    __syncthreads();

    // ---- main loop: single barrier per chunk ----
    for (int c = 0; c < NCHUNK; ++c) {
        const int s = c & 1;
        const int has_next = (c + 1) < NCHUNK;

        if (has_next) {
            ISSUE_B(s ^ 1, (c + 1) * BK);
            LOAD_A((c + 1) * BK);
        }

        // ---- compute chunk c: 4 K-steps x 20 MMAs ----
        const uint32_t b_base = sb + s * B_STAGE + boff;
        #pragma unroll
        for (int ks = 0; ks < 4; ++ks) {
            #pragma unroll
            for (int half = 0; half < 2; ++half) {
                uint32_t bf[5][4];
                #pragma unroll
                for (int g = 0; g < 5; ++g)
                    ldsm4(bf[g], b_base + (half * 5 + g) * 16 * ROWB + ks * 32);
                #pragma unroll
                for (int g = 0; g < 5; ++g) {
                    mma16816(acc[half * 10 + 2 * g],     acur[ks], bf[g][0], bf[g][1]);
                    mma16816(acc[half * 10 + 2 * g + 1], acur[ks], bf[g][2], bf[g][3]);
                }
            }
        }

        if (has_next)
            CVT_A();           // next chunk's A frags -> fp16x2
        CP_WAIT0();
        __syncthreads();       // single barrier: B stage flip
    }

    // ---- write C frags to padded smem hat tile ----
    float* hat = reinterpret_cast<float*>(smem);
    {
        const int r0 = m0 + (lane >> 2);
        const int cbase = (lane & 3) * 2;
        #pragma unroll
        for (int j = 0; j < 20; ++j) {
            const int col = cbase + 8 * j;
            hat[r0 * HAT_STRIDE + col]           = acc[j][0];
            hat[r0 * HAT_STRIDE + col + 1]       = acc[j][1];
            hat[(r0 + 8) * HAT_STRIDE + col]     = acc[j][2];
            hat[(r0 + 8) * HAT_STRIDE + col + 1] = acc[j][3];
        }
    }
    __syncthreads();

    // ---- dynamic routing: one thread per row ----
    if (tid < BM) {
        const float* h = &hat[tid * HAT_STRIDE];

        float b[NC];
        #pragma unroll
        for (int n = 0; n < NC; ++n) b[n] = 0.0f;
        float out[DC];

        #pragma unroll
        for (int it = 0; it < 3; ++it) {
            float m = b[0];
            #pragma unroll
            for (int n = 1; n < NC; ++n) m = fmaxf(m, b[n]);
            float cc[NC];
            float se = 0.0f;
            #pragma unroll
            for (int n = 0; n < NC; ++n) { cc[n] = expf(b[n] - m); se += cc[n]; }
            const float inv = 1.0f / se;

            float s[DC];
            #pragma unroll
            for (int d = 0; d < DC; ++d) s[d] = 0.0f;
            #pragma unroll
            for (int n = 0; n < NC; ++n) {
                const float cn = cc[n] * inv;
                #pragma unroll
                for (int d = 0; d < DC; ++d)
                    s[d] = fmaf(cn, h[n * DC + d], s[d]);
            }

            float s2 = 0.0f;
            #pragma unroll
            for (int d = 0; d < DC; ++d) s2 = fmaf(s[d], s[d], s2);
            const float scale = s2 / ((1.0f + s2) * sqrtf(s2 + 1e-7f));
            #pragma unroll
            for (int d = 0; d < DC; ++d) out[d] = scale * s[d];

            if (it < 2) {
                #pragma unroll
                for (int n = 0; n < NC; ++n) {
                    float dot = 0.0f;
                    #pragma unroll
                    for (int d = 0; d < DC; ++d)
                        dot = fmaf(h[n * DC + d], out[d], dot);
                    b[n] += dot;
                }
            }
        }

        float4* o = reinterpret_cast<float4*>(dout + (size_t)(rowBase + tid) * DC);
        o[0] = make_float4(out[0],  out[1],  out[2],  out[3]);
        o[1] = make_float4(out[4],  out[5],  out[6],  out[7]);
        o[2] = make_float4(out[8],  out[9],  out[10], out[11]);
        o[3] = make_float4(out[12], out[13], out[14], out[15]);
    }
}

extern "C" void kernel_launch(void* const* d_in, const int* in_sizes, int n_in,
                              void* d_out, int out_size)
{
    const float* inp = (const float*)d_in[0];
    const float* wk  = (const float*)d_in[1];
    float* out       = (float*)d_out;

    const int rows = in_sizes[0] / K_DIM;   // 16384

    wt_prep_kernel<<<(N_DIM * K_DIM + 255) / 256, 256>>>(wk);

    cudaFuncSetAttribute(caps_hmma_kernel,
                         cudaFuncAttributeMaxDynamicSharedMemorySize, SMEM_TOTAL);
    caps_hmma_kernel<<<rows / BM, NTHREAD, SMEM_TOTAL>>>(inp, out, rows);
}